// round 1
// baseline (speedup 1.0000x reference)
#include <cuda_runtime.h>

#define TX 32
#define TY 32
#define HALO 2
#define IW (TX + 2*HALO)   // 36
#define IH (TY + 2*HALO)   // 36

__device__ __forceinline__ float frcp(float x) {
    float y;
    asm("rcp.approx.ftz.f32 %0, %1;" : "=f"(y) : "f"(x));
    return y;
}

__global__ __launch_bounds__(256, 1)
void bilateral_kernel(const float* __restrict__ bright,
                      const float* __restrict__ dark,
                      const float* __restrict__ depths,
                      const float* __restrict__ s_dv,
                      const float* __restrict__ s_sv,
                      const float* __restrict__ s_de,
                      const float* __restrict__ s_eps,
                      const float* __restrict__ s_ce,
                      float* __restrict__ out,
                      int H, int W)
{
    __shared__ float sb[IH][IW];
    __shared__ float sd[IH][IW];
    __shared__ float sz[IH][IW];
    __shared__ float hb[IH][TX];
    __shared__ float hd[IH][TX];

    const int tx = threadIdx.x & 31;
    const int ty = threadIdx.x >> 5;   // 0..7

    const int x0 = blockIdx.x * TX;
    const int y0 = blockIdx.y * TY;
    const size_t base = (size_t)blockIdx.z * H * W;

    const float dv = s_dv[0];
    const float sv = s_sv[0];
    const float n_inv2dv = -0.5f * frcp(dv);   // -1/(2 dv)
    const float n_inv2sv = -0.5f * frcp(sv);   // -1/(2 sv)

    float sw[5];
    sw[0] = sw[4] = __expf(4.0f * n_inv2sv);
    sw[1] = sw[3] = __expf(1.0f * n_inv2sv);
    sw[2] = 1.0f;

    // ---- Phase 1: load padded tiles (zero outside image) ----
    for (int r = ty; r < IH; r += 8) {
        const int gy = y0 + r - HALO;
        const bool yin = (unsigned)gy < (unsigned)H;
        {
            const int gx = x0 + tx - HALO;
            const bool in = yin && ((unsigned)gx < (unsigned)W);
            const size_t gi = base + (size_t)gy * W + gx;
            sb[r][tx] = in ? bright[gi] : 0.0f;
            sd[r][tx] = in ? dark[gi]   : 0.0f;
            sz[r][tx] = in ? depths[gi] : 0.0f;
        }
        if (tx < IW - 32) {
            const int c = tx + 32;
            const int gx = x0 + c - HALO;
            const bool in = yin && ((unsigned)gx < (unsigned)W);
            const size_t gi = base + (size_t)gy * W + gx;
            sb[r][c] = in ? bright[gi] : 0.0f;
            sd[r][c] = in ? dark[gi]   : 0.0f;
            sz[r][c] = in ? depths[gi] : 0.0f;
        }
    }
    __syncthreads();

    // ---- Phase 2: horizontal depth-guided blur, all IH rows x TX cols ----
    for (int r = ty; r < IH; r += 8) {
        const int gy = y0 + r - HALO;
        float bsum = 0.0f, dsum = 0.0f;
        if ((unsigned)gy < (unsigned)H && (unsigned)(x0 + tx) < (unsigned)W) {
            const float rz = frcp(sz[r][tx + HALO]);
            float wsum = 0.0f;
            #pragma unroll
            for (int k = 0; k < 5; k++) {
                const float zp  = sz[r][tx + k];
                const float rel = fminf(fabsf(fmaf(zp, rz, -1.0f)), 1.0f);
                const float w   = __expf(rel * rel * n_inv2dv) * sw[k];
                wsum += w;
                bsum  = fmaf(w, sb[r][tx + k], bsum);
                dsum  = fmaf(w, sd[r][tx + k], dsum);
            }
            const float wi = frcp(wsum);
            bsum *= wi;
            dsum *= wi;
        }
        hb[r][tx] = bsum;
        hd[r][tx] = dsum;
    }
    __syncthreads();

    // ---- Phase 3: vertical blur + contrast-aware blend ----
    const float de  = s_de[0];
    const float eps = s_eps[0];
    const float ce  = s_ce[0];

    for (int r = ty; r < TY; r += 8) {
        const int gy = y0 + r;
        const int gx = x0 + tx;
        if ((unsigned)gy >= (unsigned)H || (unsigned)gx >= (unsigned)W) continue;

        const float rz = frcp(sz[r + HALO][tx + HALO]);
        float wsum = 0.0f, bsum = 0.0f, dsum = 0.0f;
        #pragma unroll
        for (int k = 0; k < 5; k++) {
            const float zp  = sz[r + k][tx + HALO];
            const float rel = fminf(fabsf(fmaf(zp, rz, -1.0f)), 1.0f);
            const float w   = __expf(rel * rel * n_inv2dv) * sw[k];
            wsum += w;
            bsum  = fmaf(w, hb[r + k][tx], bsum);
            dsum  = fmaf(w, hd[r + k][tx], dsum);
        }
        const float wi = frcp(wsum);
        const float bmean = bsum * wi;
        const float dmean = dsum * wi;

        const float bv = sb[r + HALO][tx + HALO];
        const float dk = sd[r + HALO][tx + HALO];

        // custom_pow(a, e) = exp(e * log(max(a, 1e-8)))
        float devb = __expf(de * __logf(fmaxf(fabsf(bv - bmean), 1e-8f))) * ce;
        float devd = fmaxf(__expf(de * __logf(fmaxf(fabsf(dk - dmean), 1e-8f))), eps);

        const float wi2 = frcp(devb + devd);
        out[base + (size_t)gy * W + gx] = (devd * bv + devb * dk) * wi2;
    }
}

extern "C" void kernel_launch(void* const* d_in, const int* in_sizes, int n_in,
                              void* d_out, int out_size)
{
    const float* bright = (const float*)d_in[0];
    const float* dark   = (const float*)d_in[1];
    const float* depths = (const float*)d_in[2];
    const float* s_dv   = (const float*)d_in[3];
    const float* s_sv   = (const float*)d_in[4];
    const float* s_de   = (const float*)d_in[5];
    const float* s_eps  = (const float*)d_in[6];
    const float* s_ce   = (const float*)d_in[7];
    float* out = (float*)d_out;

    const int H = 1024, W = 1024;
    const int B = in_sizes[0] / (H * W);

    dim3 grid((W + TX - 1) / TX, (H + TY - 1) / TY, B);
    bilateral_kernel<<<grid, 256>>>(bright, dark, depths,
                                    s_dv, s_sv, s_de, s_eps, s_ce,
                                    out, H, W);
}